// round 15
// baseline (speedup 1.0000x reference)
#include <cuda_runtime.h>
#include <cuda_bf16.h>
#include <cstdint>

#define BATCH 64
#define CH 8
#define NSTAGE 4

typedef uint32_t u32;
typedef __nv_bfloat16 bf16;

// ---------------- device scratch ----------------
__device__ float g_ctx[BATCH*32];
__device__ float g_wr[NSTAGE*BATCH*CH*CH*9];
__device__ float g_wt[NSTAGE*BATCH*CH*CH*16];
__device__ float g_wm[NSTAGE*BATCH*CH*CH*25];
__device__ __align__(16) bf16 g_wmbh[NSTAGE*BATCH*8*27*8];
__device__ __align__(16) bf16 g_wmbl[NSTAGE*BATCH*8*27*8];
__device__ __align__(16) bf16 g_wrbh[NSTAGE*BATCH*8*10*8];
__device__ __align__(16) bf16 g_wrbl[NSTAGE*BATCH*8*10*8];
__device__ __align__(16) bf16 g_wtbh[NSTAGE*BATCH*1024];
__device__ __align__(16) bf16 g_wtbl[NSTAGE*BATCH*1024];
__device__ float g_wo[BATCH*3*CH];
__device__ float g_br[NSTAGE*BATCH*CH];
__device__ float g_bt[NSTAGE*BATCH*CH];
__device__ float g_bm[NSTAGE*BATCH*CH];
__device__ float g_bo[BATCH*3];
__device__ __align__(16) float g_pos[BATCH*128*128*CH];   // pixel-major
__device__ __align__(16) float g_neg[BATCH*256*256*CH];
__device__ __align__(16) float g_mul[BATCH*256*256*CH];
__device__ __align__(16) bf16 g_xph[BATCH*128*128*CH];
__device__ __align__(16) bf16 g_xpl[BATCH*128*128*CH];
__device__ __align__(16) float g_lxp[BATCH*128*128*CH];
__device__ unsigned g_minpos[NSTAGE*BATCH*CH];
__device__ unsigned g_minneg[NSTAGE*BATCH*CH];
__device__ unsigned g_minmul[NSTAGE*BATCH*CH];

__device__ __forceinline__ float dln_f(float v, float mn) {
    float s = (v > 0.0f) ? 1.0f : -1.0f;
    float a = fabsf(v) - mn;
    return s * __logf(__logf(a + 2.718281828459045f) + 0.01f);
}

__device__ __forceinline__ void mma16816(float* c, u32 a0, u32 a1, u32 a2, u32 a3,
                                         u32 b0, u32 b1) {
    asm("mma.sync.aligned.m16n8k16.row.col.f32.bf16.bf16.f32 "
        "{%0,%1,%2,%3},{%4,%5,%6,%7},{%8,%9},{%0,%1,%2,%3};"
        : "+f"(c[0]), "+f"(c[1]), "+f"(c[2]), "+f"(c[3])
        : "r"(a0), "r"(a1), "r"(a2), "r"(a3), "r"(b0), "r"(b1));
}

__device__ __forceinline__ void ldsm4(u32& r0, u32& r1, u32& r2, u32& r3, u32 addr) {
    asm volatile("ldmatrix.sync.aligned.m8n8.x4.shared.b16 {%0,%1,%2,%3},[%4];"
                 : "=r"(r0), "=r"(r1), "=r"(r2), "=r"(r3) : "r"(addr));
}

// ---------------- gather (+ min init) ----------------
__global__ __launch_bounds__(256) void k_gather(const int* __restrict__ ids,
                                                const float* __restrict__ cc,
                                                const float* __restrict__ lat) {
    int t = blockIdx.x * 256 + threadIdx.x;
    if (t < NSTAGE * BATCH * CH) {
        g_minpos[t] = 0x7F800000u; g_minneg[t] = 0x7F800000u; g_minmul[t] = 0x7F800000u;
    }
    if (t < BATCH * 32) g_ctx[t] = cc[ids[t >> 5] * 32 + (t & 31)];
    int b = t >> 8, p = t & 255;
    const float* lb = lat + (size_t)ids[b] * (CH * 256);
    uint4 hv, lv;
    bf16* hp = (bf16*)&hv;
    bf16* lp = (bf16*)&lv;
    float lx[CH];
    #pragma unroll
    for (int c = 0; c < CH; c++) {
        float v = lb[c * 256 + p];
        bf16 h = __float2bfloat16(v);
        hp[c] = h;
        lp[c] = __float2bfloat16(v - __bfloat162float(h));
        lx[c] = __logf(fabsf(v) + 1.0f);
    }
    size_t base = (size_t)b * 256 + p;
    ((uint4*)g_xph)[base] = hv;
    ((uint4*)g_xpl)[base] = lv;
    float4* lxd = (float4*)(g_lxp + base * 8);
    lxd[0] = make_float4(lx[0], lx[1], lx[2], lx[3]);
    lxd[1] = make_float4(lx[4], lx[5], lx[6], lx[7]);
}

// ---------------- dynamic weights ----------------
__global__ void k_weights(
    const float* __restrict__ Wr, const float* __restrict__ Ur, const float* __restrict__ Vr, const float* __restrict__ Br,
    const float* __restrict__ Wt, const float* __restrict__ Ut, const float* __restrict__ Vt, const float* __restrict__ Bt,
    const float* __restrict__ Wm, const float* __restrict__ Um, const float* __restrict__ Vm, const float* __restrict__ Bm,
    const float* __restrict__ Wo, const float* __restrict__ Uo, const float* __restrict__ Vo, const float* __restrict__ Bo)
{
    int inst = blockIdx.x, b = blockIdx.y, tid = threadIdx.x;
    __shared__ float sctx[32];
    __shared__ float su[128];
    __shared__ float sv[3200];
    if (tid < 32) sctx[tid] = g_ctx[b * 32 + tid];
    __syncthreads();

    int O, KK, type = -1, stage = 0;
    const float *U, *V, *W, *Bb;
    float *gw, *gb;
    if (inst < 12) {
        type = inst >> 2; stage = inst & 3;
        O = CH;
        if (type == 0)      { KK = 9;  U = Ur; V = Vr; W = Wr; Bb = Br; gw = g_wr; gb = g_br; }
        else if (type == 1) { KK = 16; U = Ut; V = Vt; W = Wt; Bb = Bt; gw = g_wt; gb = g_bt; }
        else                { KK = 25; U = Um; V = Vm; W = Wm; Bb = Bm; gw = g_wm; gb = g_bm; }
        int uL = 16 * O, vL = 16 * CH * KK;
        U += (size_t)stage * 32 * uL; V += (size_t)stage * 32 * vL;
        W += (size_t)stage * O * CH * KK; Bb += (size_t)stage * 32 * O;
        gw += (size_t)(stage * BATCH + b) * O * CH * KK;
        gb += (size_t)(stage * BATCH + b) * O;
    } else {
        O = 3; KK = 1;
        U = Uo; V = Vo; W = Wo; Bb = Bo;
        gw = g_wo + b * 3 * CH; gb = g_bo + b * 3;
    }
    int uLen = 16 * O, vLen = 16 * CH * KK, IKK = CH * KK, wN = O * IKK;
    int sb = stage * BATCH + b;

    for (int j = tid; j < uLen; j += blockDim.x) {
        float s = 0.f;
        #pragma unroll
        for (int l = 0; l < 32; l++) s += sctx[l] * U[l * uLen + j];
        su[j] = s;
    }
    for (int j = tid; j < vLen; j += blockDim.x) {
        float s = 0.f;
        #pragma unroll
        for (int l = 0; l < 32; l++) s += sctx[l] * V[l * vLen + j];
        sv[j] = s;
    }
    __syncthreads();

    for (int widx = tid; widx < wN; widx += blockDim.x) {
        int o = widx / IKK, k = widx - o * IKK;
        float m = 0.f;
        #pragma unroll
        for (int r = 0; r < 16; r++) m += su[r * O + o] * sv[r * IKK + k];
        float w = W[widx] * (1.0f + m + 1e-3f);
        gw[widx] = w;
        if (type == 2) {
            int i = k / 25, t = k - i * 25;
            size_t d = (size_t)(sb * 8 + o) * 216 + t * 8 + i;
            bf16 h = __float2bfloat16(w);
            g_wmbh[d] = h;
            g_wmbl[d] = __float2bfloat16(w - __bfloat162float(h));
        } else if (type == 0) {
            int i = k / 9, t = k - i * 9;
            size_t d = (size_t)sb * 640 + (o * 10 + t) * 8 + i;
            bf16 h = __float2bfloat16(w);
            g_wrbh[d] = h;
            g_wrbl[d] = __float2bfloat16(w - __bfloat162float(h));
        } else if (type == 1) {
            int i = k / 16, t = k - i * 16;
            int ky = t >> 2, kx = t & 3;
            int py = (3 - ky) & 1, dy = (3 - ky) >> 1;
            int px = (3 - kx) & 1, dx = (3 - kx) >> 1;
            float wn = -w;
            size_t d = (size_t)sb * 1024 +
                       ((((size_t)(py * 2 + px) * 8 + o) * 2 + dy) * 2 + dx) * 8 + i;
            bf16 h = __float2bfloat16(wn);
            g_wtbh[d] = h;
            g_wtbl[d] = __float2bfloat16(wn - __bfloat162float(h));
        }
    }
    if (type == 2 && tid < 128) {
        int o = tid >> 4, t = 25 + ((tid >> 3) & 1), i = tid & 7;
        size_t d = (size_t)(sb * 8 + o) * 216 + t * 8 + i;
        g_wmbh[d] = __float2bfloat16(0.f);
        g_wmbl[d] = __float2bfloat16(0.f);
    }
    if (type == 0 && tid < 64) {
        int o = tid >> 3, i = tid & 7;
        size_t d = (size_t)sb * 640 + (o * 10 + 9) * 8 + i;
        g_wrbh[d] = __float2bfloat16(0.f);
        g_wrbl[d] = __float2bfloat16(0.f);
    }
    if (tid < O) {
        float s = 0.f;
        #pragma unroll
        for (int l = 0; l < 32; l++) s += sctx[l] * Bb[l * O + tid];
        gb[tid] = s;
    }
}

// ---------------- mma superkernel; grid-stride y-loops, weights staged once ----------------
template<int H>
__global__ __launch_bounds__(256) void k_mma(int stage) {
    constexpr int OH = 2 * H;
    constexpr bool TH16 = (H >= 64);
    constexpr int TH = TH16 ? 16 : 8;
    constexpr int RG = TH / 8;
    constexpr int SMSZ = TH16 ? 9440 : 6500;
    __shared__ __align__(16) u32 sm[SMSZ];
    int role = blockIdx.z >> 6;
    int b = blockIdx.z & 63;
    int tid = threadIdx.x;
    int bx = blockIdx.x, by = blockIdx.y;
    int w_ = tid >> 5, lane = tid & 31, g = lane >> 2, tg = lane & 3;
    int pix16 = (lane & 7) + ((lane >> 3) & 1) * 8;
    int qsel = lane >> 4;
    int GY = gridDim.y;

    if (role == 0) {
        // ---- conv3 mma at H res; tile 32xTH, y grid-stride ----
        constexpr int BX3 = (H >= 32) ? H / 32 : 1;
        constexpr int SQ3 = (H >= 32) ? 2 : 1;
        constexpr int IH = TH + 2;
        constexpr int XSZ = IH * 34 * 4;
        if (bx >= BX3) return;
        u32* XH = sm;
        u32* XL = sm + XSZ;
        u32* WH = sm + 2 * XSZ;
        u32* WL = WH + 320;
        float* sB = (float*)(WL + 320);
        unsigned* sMin = (unsigned*)(sB + 8);
        int x0 = bx * 32;
        const uint4* w4h = (const uint4*)(g_wrbh + (size_t)(stage * BATCH + b) * 640);
        const uint4* w4l = (const uint4*)(g_wrbl + (size_t)(stage * BATCH + b) * 640);
        if (tid < 80) { ((uint4*)WH)[tid] = w4h[tid]; ((uint4*)WL)[tid] = w4l[tid]; }
        if (tid < 8) { sB[tid] = g_br[(stage * BATCH + b) * CH + tid]; sMin[tid] = 0x7F800000u; }
        const uint4* xh4 = (const uint4*)g_xph + (size_t)b * H * H;
        const uint4* xl4 = (const uint4*)g_xpl + (size_t)b * H * H;
        float* outp = g_pos + (size_t)b * H * H * 8;
        u32 baseH = (u32)__cvta_generic_to_shared(XH);
        u32 baseL = (u32)__cvta_generic_to_shared(XL);
        u32 lb[RG];
        #pragma unroll
        for (int rgi = 0; rgi < RG; rgi++)
            lb[rgi] = (u32)(((w_ + rgi * 8) * 34 + pix16) * 16);
        float me = 3.4e38f, mo = 3.4e38f;
        float b0f, b1f;
        __syncthreads();
        b0f = sB[2 * tg]; b1f = sB[2 * tg + 1];

        for (int ty = by; ty < H / TH; ty += GY) {
            int y0 = ty * TH;
            __syncthreads();
            for (int j = tid; j < IH * 34; j += 256) {
                int r = j / 34, c = j - 34 * r;
                int gy = y0 - 1 + r, gx = x0 - 1 + c;
                uint4 v = make_uint4(0, 0, 0, 0), w2 = make_uint4(0, 0, 0, 0);
                if ((unsigned)gy < (unsigned)H && (unsigned)gx < (unsigned)H) {
                    v = xh4[gy * H + gx]; w2 = xl4[gy * H + gx];
                }
                ((uint4*)XH)[j] = v; ((uint4*)XL)[j] = w2;
            }
            __syncthreads();

            float cacc[RG][2][4];
            #pragma unroll
            for (int rgi = 0; rgi < RG; rgi++)
                #pragma unroll
                for (int s = 0; s < 2; s++) {
                    cacc[rgi][s][0] = b0f; cacc[rgi][s][1] = b1f;
                    cacc[rgi][s][2] = b0f; cacc[rgi][s][3] = b1f;
                }
            #pragma unroll
            for (int k = 0; k < 5; k++) {
                const int t0 = 2 * k, t1 = 2 * k + 1;
                const int t1c = (t1 < 9) ? t1 : 0;
                const int ky0 = t0 / 3, kx0 = t0 % 3;
                const int ky1 = t1c / 3, kx1 = t1c % 3;
                u32 bh0 = WH[(g * 10 + t0) * 4 + tg], bh1 = WH[(g * 10 + t1) * 4 + tg];
                u32 bl0 = WL[(g * 10 + t0) * 4 + tg], bl1 = WL[(g * 10 + t1) * 4 + tg];
                const int d0 = (ky0 * 34 + kx0) * 16, d1 = (ky1 * 34 + kx1) * 16;
                u32 dd = (u32)(qsel ? d1 : d0);
                #pragma unroll
                for (int rgi = 0; rgi < RG; rgi++) {
                    #pragma unroll
                    for (int s = 0; s < SQ3; s++) {
                        u32 a0h, a1h, a2h, a3h, a0l, a1l, a2l, a3l;
                        ldsm4(a0h, a1h, a2h, a3h, baseH + lb[rgi] + dd + s * 256);
                        ldsm4(a0l, a1l, a2l, a3l, baseL + lb[rgi] + dd + s * 256);
                        float* cc = cacc[rgi][s];
                        mma16816(cc, a0h, a1h, a2h, a3h, bh0, bh1);
                        mma16816(cc, a0l, a1l, a2l, a3l, bh0, bh1);
                        mma16816(cc, a0h, a1h, a2h, a3h, bl0, bl1);
                    }
                }
            }
            #pragma unroll
            for (int rgi = 0; rgi < RG; rgi++) {
                int Y = y0 + w_ + rgi * 8;
                #pragma unroll
                for (int s = 0; s < SQ3; s++) {
                    float* cc = cacc[rgi][s];
                    int X = x0 + s * 16 + g;
                    *(float2*)&outp[(size_t)(Y * H + X) * 8 + 2 * tg] = make_float2(cc[0], cc[1]);
                    *(float2*)&outp[(size_t)(Y * H + X + 8) * 8 + 2 * tg] = make_float2(cc[2], cc[3]);
                    me = fminf(me, fminf(fabsf(cc[0]), fabsf(cc[2])));
                    mo = fminf(mo, fminf(fabsf(cc[1]), fabsf(cc[3])));
                }
            }
        }
        #pragma unroll
        for (int off2 = 16; off2 >= 4; off2 >>= 1) {
            me = fminf(me, __shfl_xor_sync(0xFFFFFFFFu, me, off2));
            mo = fminf(mo, __shfl_xor_sync(0xFFFFFFFFu, mo, off2));
        }
        if (lane < 4) {
            atomicMin(&sMin[2 * tg], __float_as_uint(me));
            atomicMin(&sMin[2 * tg + 1], __float_as_uint(mo));
        }
        __syncthreads();
        if (tid < 8) atomicMin(&g_minpos[stage * BATCH * CH + b * CH + tid], sMin[tid]);

    } else if (role == 1) {
        // ---- convT mma at OH res; y grid-stride ----
        constexpr int RGT = RG;
        constexpr int IHT = TH16 ? 10 : 6;
        constexpr int XTSZ = IHT * 18 * 4;
        u32* XH = sm;
        u32* XL = sm + XTSZ;
        u32* WH = sm + 2 * XTSZ;
        u32* WL = WH + 512;
        float* sB = (float*)(WL + 512);
        unsigned* sMin = (unsigned*)(sB + 8);
        int x0 = bx * 32;
        const uint4* w4h = (const uint4*)(g_wtbh + (size_t)(stage * BATCH + b) * 1024);
        const uint4* w4l = (const uint4*)(g_wtbl + (size_t)(stage * BATCH + b) * 1024);
        if (tid < 128) { ((uint4*)WH)[tid] = w4h[tid]; ((uint4*)WL)[tid] = w4l[tid]; }
        if (tid < 8) { sB[tid] = g_bt[(stage * BATCH + b) * CH + tid]; sMin[tid] = 0x7F800000u; }
        const uint4* xh4 = (const uint4*)g_xph + (size_t)b * H * H;
        const uint4* xl4 = (const uint4*)g_xpl + (size_t)b * H * H;
        float* outp = g_neg + (size_t)b * OH * OH * 8;
        int ix0 = x0 / 2 - 1;
        int py = w_ & 1;
        float me = 3.4e38f, mo = 3.4e38f;
        float b0f, b1f;
        __syncthreads();
        b0f = sB[2 * tg]; b1f = sB[2 * tg + 1];

        for (int ty = by; ty < OH / (8 * RGT); ty += GY) {
            int y0 = ty * (8 * RGT);
            int iy0 = y0 / 2 - 1;
            __syncthreads();
            for (int j = tid; j < IHT * 18; j += 256) {
                int r = j / 18, c = j - 18 * r;
                int gy = iy0 + r, gx = ix0 + c;
                uint4 v = make_uint4(0, 0, 0, 0), w2 = make_uint4(0, 0, 0, 0);
                if ((unsigned)gy < (unsigned)H && (unsigned)gx < (unsigned)H) {
                    v = xh4[gy * H + gx]; w2 = xl4[gy * H + gx];
                }
                ((uint4*)XH)[j] = v; ((uint4*)XL)[j] = w2;
            }
            __syncthreads();

            int r0b = (w_ >> 1) + py;
            #pragma unroll
            for (int rgi = 0; rgi < RGT; rgi++) {
                int r0 = r0b + rgi * 4;
                int Y = y0 + w_ + rgi * 8;
                #pragma unroll
                for (int px = 0; px < 2; px++) {
                    float cc[4] = {b0f, b1f, b0f, b1f};
                    #pragma unroll
                    for (int dy = 0; dy < 2; dy++) {
                        int wb = ((((py * 2 + px) * 8 + g) * 2 + dy) * 2) * 4 + tg;
                        u32 bh0 = WH[wb], bh1 = WH[wb + 4];
                        u32 bl0 = WL[wb], bl1 = WL[wb + 4];
                        int base0 = ((r0 + dy) * 18 + g + px) * 4 + tg;
                        u32 a0h = XH[base0], a1h = XH[base0 + 32], a2h = XH[base0 + 4], a3h = XH[base0 + 36];
                        u32 a0l = XL[base0], a1l = XL[base0 + 32], a2l = XL[base0 + 4], a3l = XL[base0 + 36];
                        mma16816(cc, a0h, a1h, a2h, a3h, bh0, bh1);
                        mma16816(cc, a0l, a1l, a2l, a3l, bh0, bh1);
                        mma16816(cc, a0h, a1h, a2h, a3h, bl0, bl1);
                    }
                    int X0 = x0 + 2 * g + px;
                    int X1 = x0 + 2 * (g + 8) + px;
                    *(float2*)&outp[(size_t)(Y * OH + X0) * 8 + 2 * tg] = make_float2(cc[0], cc[1]);
                    *(float2*)&outp[(size_t)(Y * OH + X1) * 8 + 2 * tg] = make_float2(cc[2], cc[3]);
                    me = fminf(me, fminf(fabsf(cc[0]), fabsf(cc[2])));
                    mo = fminf(mo, fminf(fabsf(cc[1]), fabsf(cc[3])));
                }
            }
        }
        #pragma unroll
        for (int off2 = 16; off2 >= 4; off2 >>= 1) {
            me = fminf(me, __shfl_xor_sync(0xFFFFFFFFu, me, off2));
            mo = fminf(mo, __shfl_xor_sync(0xFFFFFFFFu, mo, off2));
        }
        if (lane < 4) {
            atomicMin(&sMin[2 * tg], __float_as_uint(me));
            atomicMin(&sMin[2 * tg + 1], __float_as_uint(mo));
        }
        __syncthreads();
        if (tid < 8) atomicMin(&g_minneg[stage * BATCH * CH + b * CH + tid], sMin[tid]);

    } else {
        // ---- conv5 mma at OH res; y grid-stride; in-block bilinear from lxp ----
        constexpr int LH = TH16 ? 12 : 8, LW = 20;
        constexpr int XR = TH + 4;
        constexpr int LSZ = LH * LW * 8;
        constexpr int XSZ = XR * 36 * 4;
        float* sLx = (float*)sm;
        u32* XuH = sm + LSZ;
        u32* XuL = XuH + XSZ;
        u32* WH = XuL + XSZ;
        u32* WL = WH + 864;
        float* sB = (float*)(WL + 864);
        unsigned* sMin = (unsigned*)(sB + 8);
        int x0 = bx * 32;
        const uint4* w4h = (const uint4*)(g_wmbh + (size_t)((stage * BATCH + b) * 8) * 216);
        const uint4* w4l = (const uint4*)(g_wmbl + (size_t)((stage * BATCH + b) * 8) * 216);
        if (tid < 216) { ((uint4*)WH)[tid] = w4h[tid]; ((uint4*)WL)[tid] = w4l[tid]; }
        if (tid < 8) { sB[tid] = g_bm[(stage * BATCH + b) * CH + tid]; sMin[tid] = 0x7F800000u; }
        int gxLo = ((x0 - 2) >> 1) - 1;
        const float4* lx4 = (const float4*)g_lxp + (size_t)b * H * H * 2;
        float* mulb = g_mul + (size_t)b * OH * OH * 8;
        u32 baseH = (u32)__cvta_generic_to_shared(XuH);
        u32 baseL = (u32)__cvta_generic_to_shared(XuL);
        u32 lb[RG];
        #pragma unroll
        for (int rgi = 0; rgi < RG; rgi++)
            lb[rgi] = (u32)(((w_ + rgi * 8) * 36 + pix16) * 16);
        float me = 3.4e38f, mo = 3.4e38f;
        float b0f, b1f;
        __syncthreads();
        b0f = sB[2 * tg]; b1f = sB[2 * tg + 1];

        for (int ty = by; ty < OH / TH; ty += GY) {
            int y0 = ty * TH;
            int gyLo = (y0 >> 1) - 2;
            __syncthreads();
            for (int j = tid; j < LH * LW; j += 256) {
                int r = j / LW, c = j - LW * r;
                int gy = gyLo + r, gx = gxLo + c;
                float4 v0 = make_float4(0, 0, 0, 0), v1 = make_float4(0, 0, 0, 0);
                if ((unsigned)gy < (unsigned)H && (unsigned)gx < (unsigned)H) {
                    v0 = lx4[(gy * H + gx) * 2];
                    v1 = lx4[(gy * H + gx) * 2 + 1];
                }
                ((float4*)sLx)[j * 2] = v0;
                ((float4*)sLx)[j * 2 + 1] = v1;
            }
            __syncthreads();
            bf16* xuh = (bf16*)XuH;
            bf16* xul = (bf16*)XuL;
            for (int j = tid; j < XR * 36; j += 256) {
                int r = j / 36, c = j - 36 * r;
                int Y = y0 - 2 + r, X = x0 - 2 + c;
                if ((unsigned)Y < (unsigned)OH && (unsigned)X < (unsigned)OH) {
                    int iy = Y >> 1, ix = X >> 1;
                    int yo = (Y & 1) ? min(iy + 1, H - 1) : max(iy - 1, 0);
                    int xo = (X & 1) ? min(ix + 1, H - 1) : max(ix - 1, 0);
                    int ry = iy - gyLo, ryo = yo - gyLo;
                    int cx = ix - gxLo, cxo = xo - gxLo;
                    const float4* A  = (const float4*)(sLx + (ry * LW + cx) * 8);
                    const float4* Bq = (const float4*)(sLx + (ry * LW + cxo) * 8);
                    const float4* Cq = (const float4*)(sLx + (ryo * LW + cx) * 8);
                    const float4* D  = (const float4*)(sLx + (ryo * LW + cxo) * 8);
                    #pragma unroll
                    for (int half = 0; half < 2; half++) {
                        float4 a = A[half], bb = Bq[half], cc2 = Cq[half], d = D[half];
                        float v[4];
                        v[0] = 0.5625f * a.x + 0.1875f * bb.x + 0.1875f * cc2.x + 0.0625f * d.x;
                        v[1] = 0.5625f * a.y + 0.1875f * bb.y + 0.1875f * cc2.y + 0.0625f * d.y;
                        v[2] = 0.5625f * a.z + 0.1875f * bb.z + 0.1875f * cc2.z + 0.0625f * d.z;
                        v[3] = 0.5625f * a.w + 0.1875f * bb.w + 0.1875f * cc2.w + 0.0625f * d.w;
                        #pragma unroll
                        for (int k = 0; k < 4; k++) {
                            bf16 h = __float2bfloat16(v[k]);
                            xuh[j * 8 + half * 4 + k] = h;
                            xul[j * 8 + half * 4 + k] = __float2bfloat16(v[k] - __bfloat162float(h));
                        }
                    }
                } else {
                    ((uint4*)XuH)[j] = make_uint4(0, 0, 0, 0);
                    ((uint4*)XuL)[j] = make_uint4(0, 0, 0, 0);
                }
            }
            __syncthreads();

            float cacc[RG][2][4];
            #pragma unroll
            for (int rgi = 0; rgi < RG; rgi++)
                #pragma unroll
                for (int s = 0; s < 2; s++) {
                    cacc[rgi][s][0] = b0f; cacc[rgi][s][1] = b1f;
                    cacc[rgi][s][2] = b0f; cacc[rgi][s][3] = b1f;
                }
            #pragma unroll
            for (int k = 0; k < 13; k++) {
                const int t0 = 2 * k, t1 = 2 * k + 1;
                const int ky0 = t0 / 5, kx0 = t0 % 5;
                const int ky1 = (t1 < 25) ? t1 / 5 : 0, kx1 = (t1 < 25) ? t1 % 5 : 0;
                u32 bh0 = WH[(g * 27 + t0) * 4 + tg], bh1 = WH[(g * 27 + t1) * 4 + tg];
                u32 bl0 = WL[(g * 27 + t0) * 4 + tg], bl1 = WL[(g * 27 + t1) * 4 + tg];
                const int d0 = (ky0 * 36 + kx0) * 16, d1 = (ky1 * 36 + kx1) * 16;
                u32 dd = (u32)(qsel ? d1 : d0);
                #pragma unroll
                for (int rgi = 0; rgi < RG; rgi++) {
                    #pragma unroll
                    for (int s = 0; s < 2; s++) {
                        u32 a0h, a1h, a2h, a3h, a0l, a1l, a2l, a3l;
                        ldsm4(a0h, a1h, a2h, a3h, baseH + lb[rgi] + dd + s * 256);
                        ldsm4(a0l, a1l, a2l, a3l, baseL + lb[rgi] + dd + s * 256);
                        float* cc = cacc[rgi][s];
                        mma16816(cc, a0h, a1h, a2h, a3h, bh0, bh1);
                        mma16816(cc, a0l, a1l, a2l, a3l, bh0, bh1);
                        mma16816(cc, a0h, a1h, a2h, a3h, bl0, bl1);
                    }
                }
            }
            #pragma unroll
            for (int rgi = 0; rgi < RG; rgi++) {
                int Y = y0 + w_ + rgi * 8;
                #pragma unroll
                for (int s = 0; s < 2; s++) {
                    float* cc = cacc[rgi][s];
                    int X = x0 + s * 16 + g;
                    *(float2*)&mulb[(size_t)(Y * OH + X) * 8 + 2 * tg] = make_float2(cc[0], cc[1]);
                    *(float2*)&mulb[(size_t)(Y * OH + X + 8) * 8 + 2 * tg] = make_float2(cc[2], cc[3]);
                    me = fminf(me, fminf(fabsf(cc[0]), fabsf(cc[2])));
                    mo = fminf(mo, fminf(fabsf(cc[1]), fabsf(cc[3])));
                }
            }
        }
        #pragma unroll
        for (int off2 = 16; off2 >= 4; off2 >>= 1) {
            me = fminf(me, __shfl_xor_sync(0xFFFFFFFFu, me, off2));
            mo = fminf(mo, __shfl_xor_sync(0xFFFFFFFFu, mo, off2));
        }
        if (lane < 4) {
            atomicMin(&sMin[2 * tg], __float_as_uint(me));
            atomicMin(&sMin[2 * tg + 1], __float_as_uint(mo));
        }
        __syncthreads();
        if (tid < 8) atomicMin(&g_minmul[stage * BATCH * CH + b * CH + tid], sMin[tid]);
    }
}

// ---------------- combine to pixel-major xph/xpl/lxp ----------------
template<int H>
__global__ __launch_bounds__(256) void k_combineP(int stage) {
    constexpr int OH = 2 * H;
    int b = blockIdx.y;
    int p = blockIdx.x * 256 + threadIdx.x;
    if (p >= OH * OH) return;
    int lane = threadIdx.x & 31;
    int Y = p / OH, X = p - Y * OH;
    int pp = (Y >> 1) * H + (X >> 1);
    __shared__ float sMn[3 * CH];
    if (threadIdx.x < 3 * CH) {
        int c = threadIdx.x & 7, which = threadIdx.x >> 3;
        const unsigned* src = which == 0 ? g_minpos : (which == 1 ? g_minneg : g_minmul);
        sMn[threadIdx.x] = __uint_as_float(src[stage * BATCH * CH + b * CH + c]);
    }
    __syncthreads();

    float dpv[CH];
    {
        float mydp[CH];
        if ((lane & 1) == 0) {
            const float4* p4 = (const float4*)(g_pos + ((size_t)b * H * H + pp) * 8);
            float4 a0 = p4[0], a1 = p4[1];
            float pv[8] = {a0.x, a0.y, a0.z, a0.w, a1.x, a1.y, a1.z, a1.w};
            #pragma unroll
            for (int c = 0; c < CH; c++) mydp[c] = dln_f(pv[c], sMn[c]);
        } else {
            #pragma unroll
            for (int c = 0; c < CH; c++) mydp[c] = 0.f;
        }
        #pragma unroll
        for (int c = 0; c < CH; c++)
            dpv[c] = __shfl_sync(0xFFFFFFFFu, mydp[c], lane & ~1);
    }

    float ng[CH], ml[CH];
    {
        const float4* n4 = (const float4*)(g_neg + ((size_t)b * OH * OH + p) * 8);
        const float4* m4 = (const float4*)(g_mul + ((size_t)b * OH * OH + p) * 8);
        float4 a0 = n4[0], a1 = n4[1];
        ng[0]=a0.x; ng[1]=a0.y; ng[2]=a0.z; ng[3]=a0.w;
        ng[4]=a1.x; ng[5]=a1.y; ng[6]=a1.z; ng[7]=a1.w;
        a0 = m4[0]; a1 = m4[1];
        ml[0]=a0.x; ml[1]=a0.y; ml[2]=a0.z; ml[3]=a0.w;
        ml[4]=a1.x; ml[5]=a1.y; ml[6]=a1.z; ml[7]=a1.w;
    }

    uint4 hv, lv;
    bf16* hp = (bf16*)&hv;
    bf16* lp = (bf16*)&lv;
    float lx[CH];
    #pragma unroll
    for (int c = 0; c < CH; c++) {
        float xv = (dpv[c] + dln_f(ng[c], sMn[8 + c])) * dln_f(ml[c], sMn[16 + c]);
        bf16 h = __float2bfloat16(xv);
        hp[c] = h;
        lp[c] = __float2bfloat16(xv - __bfloat162float(h));
        lx[c] = __logf(fabsf(xv) + 1.0f);
    }
    size_t base = (size_t)b * OH * OH + p;
    ((uint4*)g_xph)[base] = hv;
    ((uint4*)g_xpl)[base] = lv;
    float4* lxd = (float4*)(g_lxp + base * 8);
    lxd[0] = make_float4(lx[0], lx[1], lx[2], lx[3]);
    lxd[1] = make_float4(lx[4], lx[5], lx[6], lx[7]);
}

// ---------------- final combine + 1x1 conv ----------------
__global__ __launch_bounds__(256) void k_comfinal(float* __restrict__ out) {
    constexpr int H = 128, OH = 256;
    constexpr int stage = 3;
    int b = blockIdx.y;
    int p = blockIdx.x * 256 + threadIdx.x;
    int lane = threadIdx.x & 31;
    int Y = p >> 8, X = p & 255;
    int pp = (Y >> 1) * H + (X >> 1);
    __shared__ float sMn[3 * CH];
    __shared__ float sWo[3 * CH];
    __shared__ float sBo[3];
    if (threadIdx.x < 3 * CH) {
        int c = threadIdx.x & 7, which = threadIdx.x >> 3;
        const unsigned* src = which == 0 ? g_minpos : (which == 1 ? g_minneg : g_minmul);
        sMn[threadIdx.x] = __uint_as_float(src[stage * BATCH * CH + b * CH + c]);
        sWo[threadIdx.x] = g_wo[b * 24 + threadIdx.x];
    }
    if (threadIdx.x >= 32 && threadIdx.x < 35) sBo[threadIdx.x - 32] = g_bo[b * 3 + threadIdx.x - 32];
    __syncthreads();

    float dpv[CH];
    {
        float mydp[CH];
        if ((lane & 1) == 0) {
            const float4* p4 = (const float4*)(g_pos + ((size_t)b * H * H + pp) * 8);
            float4 a0 = p4[0], a1 = p4[1];
            float pv[8] = {a0.x, a0.y, a0.z, a0.w, a1.x, a1.y, a1.z, a1.w};
            #pragma unroll
            for (int c = 0; c < CH; c++) mydp[c] = dln_f(pv[c], sMn[c]);
        } else {
            #pragma unroll
            for (int c = 0; c < CH; c++) mydp[c] = 0.f;
        }
        #pragma unroll
        for (int c = 0; c < CH; c++)
            dpv[c] = __shfl_sync(0xFFFFFFFFu, mydp[c], lane & ~1);
    }

    const float4* n4 = (const float4*)(g_neg + ((size_t)b * OH * OH + p) * 8);
    const float4* m4 = (const float4*)(g_mul + ((size_t)b * OH * OH + p) * 8);
    float ng[8], ml[8];
    float4 a0 = n4[0], a1 = n4[1];
    ng[0]=a0.x; ng[1]=a0.y; ng[2]=a0.z; ng[3]=a0.w; ng[4]=a1.x; ng[5]=a1.y; ng[6]=a1.z; ng[7]=a1.w;
    a0 = m4[0]; a1 = m4[1];
    ml[0]=a0.x; ml[1]=a0.y; ml[2]=a0.z; ml[3]=a0.w; ml[4]=a1.x; ml[5]=a1.y; ml[6]=a1.z; ml[7]=a1.w;

    float acc[3] = {sBo[0], sBo[1], sBo[2]};
    #pragma unroll
    for (int c = 0; c < CH; c++) {
        float xv = (dpv[c] + dln_f(ng[c], sMn[8 + c])) * dln_f(ml[c], sMn[16 + c]);
        #pragma unroll
        for (int o = 0; o < 3; o++) acc[o] += sWo[o * CH + c] * xv;
    }
    #pragma unroll
    for (int o = 0; o < 3; o++)
        out[((size_t)b * 3 + o) * OH * OH + p] = acc[o];
}

// ---------------- launcher ----------------
extern "C" void kernel_launch(void* const* d_in, const int* in_sizes, int n_in,
                              void* d_out, int out_size) {
    const int*   ids = (const int*)  d_in[0];
    const float* cc  = (const float*)d_in[1];
    const float* lat = (const float*)d_in[2];
    const float* Wr = (const float*)d_in[3];
    const float* Ur = (const float*)d_in[4];
    const float* Vr = (const float*)d_in[5];
    const float* Br = (const float*)d_in[6];
    const float* Wt = (const float*)d_in[7];
    const float* Ut = (const float*)d_in[8];
    const float* Vt = (const float*)d_in[9];
    const float* Bt = (const float*)d_in[10];
    const float* Wm = (const float*)d_in[11];
    const float* Um = (const float*)d_in[12];
    const float* Vm = (const float*)d_in[13];
    const float* Bm = (const float*)d_in[14];
    const float* Wo = (const float*)d_in[15];
    const float* Uo = (const float*)d_in[16];
    const float* Vo = (const float*)d_in[17];
    const float* Bo = (const float*)d_in[18];

    k_gather<<<64, 256>>>(ids, cc, lat);
    k_weights<<<dim3(13, 64), 128>>>(Wr, Ur, Vr, Br, Wt, Ut, Vt, Bt,
                                     Wm, Um, Vm, Bm, Wo, Uo, Vo, Bo);

    // stage 0: H=16 (TH=8, trips<=1)
    k_mma<16><<<dim3(1, 4, 192), 256>>>(0);
    k_combineP<16><<<dim3(4, 64), 256>>>(0);
    // stage 1: H=32 (TH=8, trips<=1)
    k_mma<32><<<dim3(2, 8, 192), 256>>>(1);
    k_combineP<32><<<dim3(16, 64), 256>>>(1);
    // stage 2: H=64 (TH=16, YLOOP=2)
    k_mma<64><<<dim3(4, 4, 192), 256>>>(2);
    k_combineP<64><<<dim3(64, 64), 256>>>(2);
    // stage 3: H=128 (TH=16, YLOOP=4)
    k_mma<128><<<dim3(8, 4, 192), 256>>>(3);
    k_comfinal<<<dim3(256, 64), 256>>>((float*)d_out);
}

// round 16
// speedup vs baseline: 1.0442x; 1.0442x over previous
#include <cuda_runtime.h>
#include <cuda_bf16.h>
#include <cstdint>

#define BATCH 64
#define CH 8
#define NSTAGE 4

typedef uint32_t u32;
typedef __nv_bfloat16 bf16;

// ---------------- device scratch ----------------
__device__ float g_ctx[BATCH*32];
__device__ float g_wr[NSTAGE*BATCH*CH*CH*9];
__device__ float g_wt[NSTAGE*BATCH*CH*CH*16];
__device__ float g_wm[NSTAGE*BATCH*CH*CH*25];
__device__ __align__(16) bf16 g_wmbh[NSTAGE*BATCH*8*27*8];
__device__ __align__(16) bf16 g_wmbl[NSTAGE*BATCH*8*27*8];
__device__ __align__(16) bf16 g_wrbh[NSTAGE*BATCH*8*10*8];
__device__ __align__(16) bf16 g_wrbl[NSTAGE*BATCH*8*10*8];
__device__ __align__(16) bf16 g_wtbh[NSTAGE*BATCH*1024];
__device__ __align__(16) bf16 g_wtbl[NSTAGE*BATCH*1024];
__device__ float g_wo[BATCH*3*CH];
__device__ float g_br[NSTAGE*BATCH*CH];
__device__ float g_bt[NSTAGE*BATCH*CH];
__device__ float g_bm[NSTAGE*BATCH*CH];
__device__ float g_bo[BATCH*3];
__device__ __align__(16) float g_pos[BATCH*128*128*CH];   // pixel-major
__device__ __align__(16) float g_neg[BATCH*256*256*CH];
__device__ __align__(16) float g_mul[BATCH*256*256*CH];
__device__ __align__(16) bf16 g_xph[BATCH*128*128*CH];
__device__ __align__(16) bf16 g_xpl[BATCH*128*128*CH];
__device__ __align__(16) float g_lxp[BATCH*128*128*CH];
__device__ unsigned g_minpos[NSTAGE*BATCH*CH];
__device__ unsigned g_minneg[NSTAGE*BATCH*CH];
__device__ unsigned g_minmul[NSTAGE*BATCH*CH];

__device__ __forceinline__ float dln_f(float v, float mn) {
    float s = (v > 0.0f) ? 1.0f : -1.0f;
    float a = fabsf(v) - mn;
    return s * __logf(__logf(a + 2.718281828459045f) + 0.01f);
}

__device__ __forceinline__ void mma16816(float* c, u32 a0, u32 a1, u32 a2, u32 a3,
                                         u32 b0, u32 b1) {
    asm("mma.sync.aligned.m16n8k16.row.col.f32.bf16.bf16.f32 "
        "{%0,%1,%2,%3},{%4,%5,%6,%7},{%8,%9},{%0,%1,%2,%3};"
        : "+f"(c[0]), "+f"(c[1]), "+f"(c[2]), "+f"(c[3])
        : "r"(a0), "r"(a1), "r"(a2), "r"(a3), "r"(b0), "r"(b1));
}

__device__ __forceinline__ void ldsm4(u32& r0, u32& r1, u32& r2, u32& r3, u32 addr) {
    asm volatile("ldmatrix.sync.aligned.m8n8.x4.shared.b16 {%0,%1,%2,%3},[%4];"
                 : "=r"(r0), "=r"(r1), "=r"(r2), "=r"(r3) : "r"(addr));
}

// ---------------- gather (+ min init) ----------------
__global__ __launch_bounds__(256) void k_gather(const int* __restrict__ ids,
                                                const float* __restrict__ cc,
                                                const float* __restrict__ lat) {
    int t = blockIdx.x * 256 + threadIdx.x;
    if (t < NSTAGE * BATCH * CH) {
        g_minpos[t] = 0x7F800000u; g_minneg[t] = 0x7F800000u; g_minmul[t] = 0x7F800000u;
    }
    if (t < BATCH * 32) g_ctx[t] = cc[ids[t >> 5] * 32 + (t & 31)];
    int b = t >> 8, p = t & 255;
    const float* lb = lat + (size_t)ids[b] * (CH * 256);
    uint4 hv, lv;
    bf16* hp = (bf16*)&hv;
    bf16* lp = (bf16*)&lv;
    float lx[CH];
    #pragma unroll
    for (int c = 0; c < CH; c++) {
        float v = lb[c * 256 + p];
        bf16 h = __float2bfloat16(v);
        hp[c] = h;
        lp[c] = __float2bfloat16(v - __bfloat162float(h));
        lx[c] = __logf(fabsf(v) + 1.0f);
    }
    size_t base = (size_t)b * 256 + p;
    ((uint4*)g_xph)[base] = hv;
    ((uint4*)g_xpl)[base] = lv;
    float4* lxd = (float4*)(g_lxp + base * 8);
    lxd[0] = make_float4(lx[0], lx[1], lx[2], lx[3]);
    lxd[1] = make_float4(lx[4], lx[5], lx[6], lx[7]);
}

// ---------------- dynamic weights ----------------
__global__ void k_weights(
    const float* __restrict__ Wr, const float* __restrict__ Ur, const float* __restrict__ Vr, const float* __restrict__ Br,
    const float* __restrict__ Wt, const float* __restrict__ Ut, const float* __restrict__ Vt, const float* __restrict__ Bt,
    const float* __restrict__ Wm, const float* __restrict__ Um, const float* __restrict__ Vm, const float* __restrict__ Bm,
    const float* __restrict__ Wo, const float* __restrict__ Uo, const float* __restrict__ Vo, const float* __restrict__ Bo)
{
    int inst = blockIdx.x, b = blockIdx.y, tid = threadIdx.x;
    __shared__ float sctx[32];
    __shared__ float su[128];
    __shared__ float sv[3200];
    if (tid < 32) sctx[tid] = g_ctx[b * 32 + tid];
    __syncthreads();

    int O, KK, type = -1, stage = 0;
    const float *U, *V, *W, *Bb;
    float *gw, *gb;
    if (inst < 12) {
        type = inst >> 2; stage = inst & 3;
        O = CH;
        if (type == 0)      { KK = 9;  U = Ur; V = Vr; W = Wr; Bb = Br; gw = g_wr; gb = g_br; }
        else if (type == 1) { KK = 16; U = Ut; V = Vt; W = Wt; Bb = Bt; gw = g_wt; gb = g_bt; }
        else                { KK = 25; U = Um; V = Vm; W = Wm; Bb = Bm; gw = g_wm; gb = g_bm; }
        int uL = 16 * O, vL = 16 * CH * KK;
        U += (size_t)stage * 32 * uL; V += (size_t)stage * 32 * vL;
        W += (size_t)stage * O * CH * KK; Bb += (size_t)stage * 32 * O;
        gw += (size_t)(stage * BATCH + b) * O * CH * KK;
        gb += (size_t)(stage * BATCH + b) * O;
    } else {
        O = 3; KK = 1;
        U = Uo; V = Vo; W = Wo; Bb = Bo;
        gw = g_wo + b * 3 * CH; gb = g_bo + b * 3;
    }
    int uLen = 16 * O, vLen = 16 * CH * KK, IKK = CH * KK, wN = O * IKK;
    int sb = stage * BATCH + b;

    for (int j = tid; j < uLen; j += blockDim.x) {
        float s = 0.f;
        #pragma unroll
        for (int l = 0; l < 32; l++) s += sctx[l] * U[l * uLen + j];
        su[j] = s;
    }
    for (int j = tid; j < vLen; j += blockDim.x) {
        float s = 0.f;
        #pragma unroll
        for (int l = 0; l < 32; l++) s += sctx[l] * V[l * vLen + j];
        sv[j] = s;
    }
    __syncthreads();

    for (int widx = tid; widx < wN; widx += blockDim.x) {
        int o = widx / IKK, k = widx - o * IKK;
        float m = 0.f;
        #pragma unroll
        for (int r = 0; r < 16; r++) m += su[r * O + o] * sv[r * IKK + k];
        float w = W[widx] * (1.0f + m + 1e-3f);
        gw[widx] = w;
        if (type == 2) {
            int i = k / 25, t = k - i * 25;
            size_t d = (size_t)(sb * 8 + o) * 216 + t * 8 + i;
            bf16 h = __float2bfloat16(w);
            g_wmbh[d] = h;
            g_wmbl[d] = __float2bfloat16(w - __bfloat162float(h));
        } else if (type == 0) {
            int i = k / 9, t = k - i * 9;
            size_t d = (size_t)sb * 640 + (o * 10 + t) * 8 + i;
            bf16 h = __float2bfloat16(w);
            g_wrbh[d] = h;
            g_wrbl[d] = __float2bfloat16(w - __bfloat162float(h));
        } else if (type == 1) {
            int i = k / 16, t = k - i * 16;
            int ky = t >> 2, kx = t & 3;
            int py = (3 - ky) & 1, dy = (3 - ky) >> 1;
            int px = (3 - kx) & 1, dx = (3 - kx) >> 1;
            float wn = -w;
            size_t d = (size_t)sb * 1024 +
                       ((((size_t)(py * 2 + px) * 8 + o) * 2 + dy) * 2 + dx) * 8 + i;
            bf16 h = __float2bfloat16(wn);
            g_wtbh[d] = h;
            g_wtbl[d] = __float2bfloat16(wn - __bfloat162float(h));
        }
    }
    if (type == 2 && tid < 128) {
        int o = tid >> 4, t = 25 + ((tid >> 3) & 1), i = tid & 7;
        size_t d = (size_t)(sb * 8 + o) * 216 + t * 8 + i;
        g_wmbh[d] = __float2bfloat16(0.f);
        g_wmbl[d] = __float2bfloat16(0.f);
    }
    if (type == 0 && tid < 64) {
        int o = tid >> 3, i = tid & 7;
        size_t d = (size_t)sb * 640 + (o * 10 + 9) * 8 + i;
        g_wrbh[d] = __float2bfloat16(0.f);
        g_wrbl[d] = __float2bfloat16(0.f);
    }
    if (tid < O) {
        float s = 0.f;
        #pragma unroll
        for (int l = 0; l < 32; l++) s += sctx[l] * Bb[l * O + tid];
        gb[tid] = s;
    }
}

// ---------------- mma superkernel; TH=16 tiles at H>=64, TH=8 below ----------------
template<int H>
__global__ __launch_bounds__(256) void k_mma(int stage) {
    constexpr int OH = 2 * H;
    constexpr bool TH16 = (H >= 64);
    constexpr int TH = TH16 ? 16 : 8;
    constexpr int RG = TH / 8;
    constexpr int SMSZ = TH16 ? 9440 : 6500;
    __shared__ __align__(16) u32 sm[SMSZ];
    int role = blockIdx.z >> 6;
    int b = blockIdx.z & 63;
    int tid = threadIdx.x;
    int bx = blockIdx.x, by = blockIdx.y;
    int w_ = tid >> 5, lane = tid & 31, g = lane >> 2, tg = lane & 3;
    int pix16 = (lane & 7) + ((lane >> 3) & 1) * 8;
    int qsel = lane >> 4;

    if (role == 0) {
        // ---- conv3 mma at H res; tile 32xTH ----
        constexpr int BX3 = (H >= 32) ? H / 32 : 1;
        constexpr int SQ3 = (H >= 32) ? 2 : 1;
        constexpr int IH = TH + 2;
        constexpr int XSZ = IH * 34 * 4;
        if (bx >= BX3 || by >= H / TH) return;
        u32* XH = sm;
        u32* XL = sm + XSZ;
        u32* WH = sm + 2 * XSZ;
        u32* WL = WH + 320;
        float* sB = (float*)(WL + 320);
        unsigned* sMin = (unsigned*)(sB + 8);
        int x0 = bx * 32, y0 = by * TH;
        const uint4* w4h = (const uint4*)(g_wrbh + (size_t)(stage * BATCH + b) * 640);
        const uint4* w4l = (const uint4*)(g_wrbl + (size_t)(stage * BATCH + b) * 640);
        if (tid < 80) { ((uint4*)WH)[tid] = w4h[tid]; ((uint4*)WL)[tid] = w4l[tid]; }
        if (tid < 8) { sB[tid] = g_br[(stage * BATCH + b) * CH + tid]; sMin[tid] = 0x7F800000u; }
        const uint4* xh4 = (const uint4*)g_xph + (size_t)b * H * H;
        const uint4* xl4 = (const uint4*)g_xpl + (size_t)b * H * H;
        for (int j = tid; j < IH * 34; j += 256) {
            int r = j / 34, c = j - 34 * r;
            int gy = y0 - 1 + r, gx = x0 - 1 + c;
            uint4 v = make_uint4(0, 0, 0, 0), w2 = make_uint4(0, 0, 0, 0);
            if ((unsigned)gy < (unsigned)H && (unsigned)gx < (unsigned)H) {
                v = xh4[gy * H + gx]; w2 = xl4[gy * H + gx];
            }
            ((uint4*)XH)[j] = v; ((uint4*)XL)[j] = w2;
        }
        __syncthreads();

        u32 baseH = (u32)__cvta_generic_to_shared(XH);
        u32 baseL = (u32)__cvta_generic_to_shared(XL);
        u32 lb[RG];
        #pragma unroll
        for (int rgi = 0; rgi < RG; rgi++)
            lb[rgi] = (u32)(((w_ + rgi * 8) * 34 + pix16) * 16);

        float b0f = sB[2 * tg], b1f = sB[2 * tg + 1];
        float cacc[RG][2][4];
        #pragma unroll
        for (int rgi = 0; rgi < RG; rgi++)
            #pragma unroll
            for (int s = 0; s < 2; s++) {
                cacc[rgi][s][0] = b0f; cacc[rgi][s][1] = b1f;
                cacc[rgi][s][2] = b0f; cacc[rgi][s][3] = b1f;
            }
        #pragma unroll
        for (int k = 0; k < 5; k++) {
            const int t0 = 2 * k, t1 = 2 * k + 1;
            const int t1c = (t1 < 9) ? t1 : 0;
            const int ky0 = t0 / 3, kx0 = t0 % 3;
            const int ky1 = t1c / 3, kx1 = t1c % 3;
            u32 bh0 = WH[(g * 10 + t0) * 4 + tg], bh1 = WH[(g * 10 + t1) * 4 + tg];
            u32 bl0 = WL[(g * 10 + t0) * 4 + tg], bl1 = WL[(g * 10 + t1) * 4 + tg];
            const int d0 = (ky0 * 34 + kx0) * 16, d1 = (ky1 * 34 + kx1) * 16;
            u32 dd = (u32)(qsel ? d1 : d0);
            #pragma unroll
            for (int rgi = 0; rgi < RG; rgi++) {
                #pragma unroll
                for (int s = 0; s < SQ3; s++) {
                    u32 a0h, a1h, a2h, a3h, a0l, a1l, a2l, a3l;
                    ldsm4(a0h, a1h, a2h, a3h, baseH + lb[rgi] + dd + s * 256);
                    ldsm4(a0l, a1l, a2l, a3l, baseL + lb[rgi] + dd + s * 256);
                    float* cc = cacc[rgi][s];
                    mma16816(cc, a0h, a1h, a2h, a3h, bh0, bh1);
                    mma16816(cc, a0l, a1l, a2l, a3l, bh0, bh1);
                    mma16816(cc, a0h, a1h, a2h, a3h, bl0, bl1);
                }
            }
        }
        float* outp = g_pos + (size_t)b * H * H * 8;
        float me = 3.4e38f, mo = 3.4e38f;
        #pragma unroll
        for (int rgi = 0; rgi < RG; rgi++) {
            int Y = y0 + w_ + rgi * 8;
            #pragma unroll
            for (int s = 0; s < SQ3; s++) {
                float* cc = cacc[rgi][s];
                int X = x0 + s * 16 + g;
                *(float2*)&outp[(size_t)(Y * H + X) * 8 + 2 * tg] = make_float2(cc[0], cc[1]);
                *(float2*)&outp[(size_t)(Y * H + X + 8) * 8 + 2 * tg] = make_float2(cc[2], cc[3]);
                me = fminf(me, fminf(fabsf(cc[0]), fabsf(cc[2])));
                mo = fminf(mo, fminf(fabsf(cc[1]), fabsf(cc[3])));
            }
        }
        #pragma unroll
        for (int off2 = 16; off2 >= 4; off2 >>= 1) {
            me = fminf(me, __shfl_xor_sync(0xFFFFFFFFu, me, off2));
            mo = fminf(mo, __shfl_xor_sync(0xFFFFFFFFu, mo, off2));
        }
        if (lane < 4) {
            atomicMin(&sMin[2 * tg], __float_as_uint(me));
            atomicMin(&sMin[2 * tg + 1], __float_as_uint(mo));
        }
        __syncthreads();
        if (tid < 8) atomicMin(&g_minpos[stage * BATCH * CH + b * CH + tid], sMin[tid]);

    } else if (role == 1) {
        // ---- convT mma at OH res; RGT rows per warp ----
        constexpr int RGT = RG;
        constexpr int IHT = TH16 ? 10 : 6;
        constexpr int XTSZ = IHT * 18 * 4;
        u32* XH = sm;
        u32* XL = sm + XTSZ;
        u32* WH = sm + 2 * XTSZ;
        u32* WL = WH + 512;
        float* sB = (float*)(WL + 512);
        unsigned* sMin = (unsigned*)(sB + 8);
        int x0 = bx * 32, y0 = by * (8 * RGT);
        const uint4* w4h = (const uint4*)(g_wtbh + (size_t)(stage * BATCH + b) * 1024);
        const uint4* w4l = (const uint4*)(g_wtbl + (size_t)(stage * BATCH + b) * 1024);
        if (tid < 128) { ((uint4*)WH)[tid] = w4h[tid]; ((uint4*)WL)[tid] = w4l[tid]; }
        if (tid < 8) { sB[tid] = g_bt[(stage * BATCH + b) * CH + tid]; sMin[tid] = 0x7F800000u; }
        int iy0 = y0 / 2 - 1, ix0 = x0 / 2 - 1;
        const uint4* xh4 = (const uint4*)g_xph + (size_t)b * H * H;
        const uint4* xl4 = (const uint4*)g_xpl + (size_t)b * H * H;
        for (int j = tid; j < IHT * 18; j += 256) {
            int r = j / 18, c = j - 18 * r;
            int gy = iy0 + r, gx = ix0 + c;
            uint4 v = make_uint4(0, 0, 0, 0), w2 = make_uint4(0, 0, 0, 0);
            if ((unsigned)gy < (unsigned)H && (unsigned)gx < (unsigned)H) {
                v = xh4[gy * H + gx]; w2 = xl4[gy * H + gx];
            }
            ((uint4*)XH)[j] = v; ((uint4*)XL)[j] = w2;
        }
        __syncthreads();

        int py = w_ & 1;
        int r0b = (w_ >> 1) + py;
        float b0f = sB[2 * tg], b1f = sB[2 * tg + 1];
        float* outp = g_neg + (size_t)b * OH * OH * 8;
        float me = 3.4e38f, mo = 3.4e38f;
        #pragma unroll
        for (int rgi = 0; rgi < RGT; rgi++) {
            int r0 = r0b + rgi * 4;
            int Y = y0 + w_ + rgi * 8;
            #pragma unroll
            for (int px = 0; px < 2; px++) {
                float cc[4] = {b0f, b1f, b0f, b1f};
                #pragma unroll
                for (int dy = 0; dy < 2; dy++) {
                    int wb = ((((py * 2 + px) * 8 + g) * 2 + dy) * 2) * 4 + tg;
                    u32 bh0 = WH[wb], bh1 = WH[wb + 4];
                    u32 bl0 = WL[wb], bl1 = WL[wb + 4];
                    int base0 = ((r0 + dy) * 18 + g + px) * 4 + tg;
                    u32 a0h = XH[base0], a1h = XH[base0 + 32], a2h = XH[base0 + 4], a3h = XH[base0 + 36];
                    u32 a0l = XL[base0], a1l = XL[base0 + 32], a2l = XL[base0 + 4], a3l = XL[base0 + 36];
                    mma16816(cc, a0h, a1h, a2h, a3h, bh0, bh1);
                    mma16816(cc, a0l, a1l, a2l, a3l, bh0, bh1);
                    mma16816(cc, a0h, a1h, a2h, a3h, bl0, bl1);
                }
                int X0 = x0 + 2 * g + px;
                int X1 = x0 + 2 * (g + 8) + px;
                *(float2*)&outp[(size_t)(Y * OH + X0) * 8 + 2 * tg] = make_float2(cc[0], cc[1]);
                *(float2*)&outp[(size_t)(Y * OH + X1) * 8 + 2 * tg] = make_float2(cc[2], cc[3]);
                me = fminf(me, fminf(fabsf(cc[0]), fabsf(cc[2])));
                mo = fminf(mo, fminf(fabsf(cc[1]), fabsf(cc[3])));
            }
        }
        #pragma unroll
        for (int off2 = 16; off2 >= 4; off2 >>= 1) {
            me = fminf(me, __shfl_xor_sync(0xFFFFFFFFu, me, off2));
            mo = fminf(mo, __shfl_xor_sync(0xFFFFFFFFu, mo, off2));
        }
        if (lane < 4) {
            atomicMin(&sMin[2 * tg], __float_as_uint(me));
            atomicMin(&sMin[2 * tg + 1], __float_as_uint(mo));
        }
        __syncthreads();
        if (tid < 8) atomicMin(&g_minneg[stage * BATCH * CH + b * CH + tid], sMin[tid]);

    } else {
        // ---- conv5 mma at OH res; tile 32xTH; in-block bilinear from lxp ----
        constexpr int LH = TH16 ? 12 : 8, LW = 20;
        constexpr int XR = TH + 4;
        constexpr int LSZ = LH * LW * 8;       // f32 count
        constexpr int XSZ = XR * 36 * 4;       // u32 per buffer
        float* sLx = (float*)sm;
        u32* XuH = sm + LSZ;
        u32* XuL = XuH + XSZ;
        u32* WH = XuL + XSZ;
        u32* WL = WH + 864;
        float* sB = (float*)(WL + 864);
        unsigned* sMin = (unsigned*)(sB + 8);
        int x0 = bx * 32, y0 = by * TH;
        const uint4* w4h = (const uint4*)(g_wmbh + (size_t)((stage * BATCH + b) * 8) * 216);
        const uint4* w4l = (const uint4*)(g_wmbl + (size_t)((stage * BATCH + b) * 8) * 216);
        if (tid < 216) { ((uint4*)WH)[tid] = w4h[tid]; ((uint4*)WL)[tid] = w4l[tid]; }
        if (tid < 8) { sB[tid] = g_bm[(stage * BATCH + b) * CH + tid]; sMin[tid] = 0x7F800000u; }

        int gyLo = (y0 >> 1) - 2;
        int gxLo = ((x0 - 2) >> 1) - 1;
        const float4* lx4 = (const float4*)g_lxp + (size_t)b * H * H * 2;
        for (int j = tid; j < LH * LW; j += 256) {
            int r = j / LW, c = j - LW * r;
            int gy = gyLo + r, gx = gxLo + c;
            float4 v0 = make_float4(0, 0, 0, 0), v1 = make_float4(0, 0, 0, 0);
            if ((unsigned)gy < (unsigned)H && (unsigned)gx < (unsigned)H) {
                v0 = lx4[(gy * H + gx) * 2];
                v1 = lx4[(gy * H + gx) * 2 + 1];
            }
            ((float4*)sLx)[j * 2] = v0;
            ((float4*)sLx)[j * 2 + 1] = v1;
        }
        __syncthreads();
        bf16* xuh = (bf16*)XuH;
        bf16* xul = (bf16*)XuL;
        for (int j = tid; j < XR * 36; j += 256) {
            int r = j / 36, c = j - 36 * r;
            int Y = y0 - 2 + r, X = x0 - 2 + c;
            if ((unsigned)Y < (unsigned)OH && (unsigned)X < (unsigned)OH) {
                int iy = Y >> 1, ix = X >> 1;
                int yo = (Y & 1) ? min(iy + 1, H - 1) : max(iy - 1, 0);
                int xo = (X & 1) ? min(ix + 1, H - 1) : max(ix - 1, 0);
                int ry = iy - gyLo, ryo = yo - gyLo;
                int cx = ix - gxLo, cxo = xo - gxLo;
                const float4* A  = (const float4*)(sLx + (ry * LW + cx) * 8);
                const float4* Bq = (const float4*)(sLx + (ry * LW + cxo) * 8);
                const float4* Cq = (const float4*)(sLx + (ryo * LW + cx) * 8);
                const float4* D  = (const float4*)(sLx + (ryo * LW + cxo) * 8);
                #pragma unroll
                for (int half = 0; half < 2; half++) {
                    float4 a = A[half], bb = Bq[half], cc2 = Cq[half], d = D[half];
                    float v[4];
                    v[0] = 0.5625f * a.x + 0.1875f * bb.x + 0.1875f * cc2.x + 0.0625f * d.x;
                    v[1] = 0.5625f * a.y + 0.1875f * bb.y + 0.1875f * cc2.y + 0.0625f * d.y;
                    v[2] = 0.5625f * a.z + 0.1875f * bb.z + 0.1875f * cc2.z + 0.0625f * d.z;
                    v[3] = 0.5625f * a.w + 0.1875f * bb.w + 0.1875f * cc2.w + 0.0625f * d.w;
                    #pragma unroll
                    for (int k = 0; k < 4; k++) {
                        bf16 h = __float2bfloat16(v[k]);
                        xuh[j * 8 + half * 4 + k] = h;
                        xul[j * 8 + half * 4 + k] = __float2bfloat16(v[k] - __bfloat162float(h));
                    }
                }
            } else {
                ((uint4*)XuH)[j] = make_uint4(0, 0, 0, 0);
                ((uint4*)XuL)[j] = make_uint4(0, 0, 0, 0);
            }
        }
        __syncthreads();

        u32 baseH = (u32)__cvta_generic_to_shared(XuH);
        u32 baseL = (u32)__cvta_generic_to_shared(XuL);
        u32 lb[RG];
        #pragma unroll
        for (int rgi = 0; rgi < RG; rgi++)
            lb[rgi] = (u32)(((w_ + rgi * 8) * 36 + pix16) * 16);

        float b0f = sB[2 * tg], b1f = sB[2 * tg + 1];
        float cacc[RG][2][4];
        #pragma unroll
        for (int rgi = 0; rgi < RG; rgi++)
            #pragma unroll
            for (int s = 0; s < 2; s++) {
                cacc[rgi][s][0] = b0f; cacc[rgi][s][1] = b1f;
                cacc[rgi][s][2] = b0f; cacc[rgi][s][3] = b1f;
            }
        #pragma unroll
        for (int k = 0; k < 13; k++) {
            const int t0 = 2 * k, t1 = 2 * k + 1;
            const int ky0 = t0 / 5, kx0 = t0 % 5;
            const int ky1 = (t1 < 25) ? t1 / 5 : 0, kx1 = (t1 < 25) ? t1 % 5 : 0;
            u32 bh0 = WH[(g * 27 + t0) * 4 + tg], bh1 = WH[(g * 27 + t1) * 4 + tg];
            u32 bl0 = WL[(g * 27 + t0) * 4 + tg], bl1 = WL[(g * 27 + t1) * 4 + tg];
            const int d0 = (ky0 * 36 + kx0) * 16, d1 = (ky1 * 36 + kx1) * 16;
            u32 dd = (u32)(qsel ? d1 : d0);
            #pragma unroll
            for (int rgi = 0; rgi < RG; rgi++) {
                #pragma unroll
                for (int s = 0; s < 2; s++) {
                    u32 a0h, a1h, a2h, a3h, a0l, a1l, a2l, a3l;
                    ldsm4(a0h, a1h, a2h, a3h, baseH + lb[rgi] + dd + s * 256);
                    ldsm4(a0l, a1l, a2l, a3l, baseL + lb[rgi] + dd + s * 256);
                    float* cc = cacc[rgi][s];
                    mma16816(cc, a0h, a1h, a2h, a3h, bh0, bh1);
                    mma16816(cc, a0l, a1l, a2l, a3l, bh0, bh1);
                    mma16816(cc, a0h, a1h, a2h, a3h, bl0, bl1);
                }
            }
        }
        float* mulb = g_mul + (size_t)b * OH * OH * 8;
        float me = 3.4e38f, mo = 3.4e38f;
        #pragma unroll
        for (int rgi = 0; rgi < RG; rgi++) {
            int Y = y0 + w_ + rgi * 8;
            #pragma unroll
            for (int s = 0; s < 2; s++) {
                float* cc = cacc[rgi][s];
                int X = x0 + s * 16 + g;
                *(float2*)&mulb[(size_t)(Y * OH + X) * 8 + 2 * tg] = make_float2(cc[0], cc[1]);
                *(float2*)&mulb[(size_t)(Y * OH + X + 8) * 8 + 2 * tg] = make_float2(cc[2], cc[3]);
                me = fminf(me, fminf(fabsf(cc[0]), fabsf(cc[2])));
                mo = fminf(mo, fminf(fabsf(cc[1]), fabsf(cc[3])));
            }
        }
        #pragma unroll
        for (int off2 = 16; off2 >= 4; off2 >>= 1) {
            me = fminf(me, __shfl_xor_sync(0xFFFFFFFFu, me, off2));
            mo = fminf(mo, __shfl_xor_sync(0xFFFFFFFFu, mo, off2));
        }
        if (lane < 4) {
            atomicMin(&sMin[2 * tg], __float_as_uint(me));
            atomicMin(&sMin[2 * tg + 1], __float_as_uint(mo));
        }
        __syncthreads();
        if (tid < 8) atomicMin(&g_minmul[stage * BATCH * CH + b * CH + tid], sMin[tid]);
    }
}

// ---------------- combine to pixel-major xph/xpl/lxp ----------------
template<int H>
__global__ __launch_bounds__(256) void k_combineP(int stage) {
    constexpr int OH = 2 * H;
    int b = blockIdx.y;
    int p = blockIdx.x * 256 + threadIdx.x;
    if (p >= OH * OH) return;
    int lane = threadIdx.x & 31;
    int Y = p / OH, X = p - Y * OH;
    int pp = (Y >> 1) * H + (X >> 1);
    __shared__ float sMn[3 * CH];
    if (threadIdx.x < 3 * CH) {
        int c = threadIdx.x & 7, which = threadIdx.x >> 3;
        const unsigned* src = which == 0 ? g_minpos : (which == 1 ? g_minneg : g_minmul);
        sMn[threadIdx.x] = __uint_as_float(src[stage * BATCH * CH + b * CH + c]);
    }
    __syncthreads();

    float dpv[CH];
    {
        float mydp[CH];
        if ((lane & 1) == 0) {
            const float4* p4 = (const float4*)(g_pos + ((size_t)b * H * H + pp) * 8);
            float4 a0 = p4[0], a1 = p4[1];
            float pv[8] = {a0.x, a0.y, a0.z, a0.w, a1.x, a1.y, a1.z, a1.w};
            #pragma unroll
            for (int c = 0; c < CH; c++) mydp[c] = dln_f(pv[c], sMn[c]);
        } else {
            #pragma unroll
            for (int c = 0; c < CH; c++) mydp[c] = 0.f;
        }
        #pragma unroll
        for (int c = 0; c < CH; c++)
            dpv[c] = __shfl_sync(0xFFFFFFFFu, mydp[c], lane & ~1);
    }

    float ng[CH], ml[CH];
    {
        const float4* n4 = (const float4*)(g_neg + ((size_t)b * OH * OH + p) * 8);
        const float4* m4 = (const float4*)(g_mul + ((size_t)b * OH * OH + p) * 8);
        float4 a0 = n4[0], a1 = n4[1];
        ng[0]=a0.x; ng[1]=a0.y; ng[2]=a0.z; ng[3]=a0.w;
        ng[4]=a1.x; ng[5]=a1.y; ng[6]=a1.z; ng[7]=a1.w;
        a0 = m4[0]; a1 = m4[1];
        ml[0]=a0.x; ml[1]=a0.y; ml[2]=a0.z; ml[3]=a0.w;
        ml[4]=a1.x; ml[5]=a1.y; ml[6]=a1.z; ml[7]=a1.w;
    }

    uint4 hv, lv;
    bf16* hp = (bf16*)&hv;
    bf16* lp = (bf16*)&lv;
    float lx[CH];
    #pragma unroll
    for (int c = 0; c < CH; c++) {
        float xv = (dpv[c] + dln_f(ng[c], sMn[8 + c])) * dln_f(ml[c], sMn[16 + c]);
        bf16 h = __float2bfloat16(xv);
        hp[c] = h;
        lp[c] = __float2bfloat16(xv - __bfloat162float(h));
        lx[c] = __logf(fabsf(xv) + 1.0f);
    }
    size_t base = (size_t)b * OH * OH + p;
    ((uint4*)g_xph)[base] = hv;
    ((uint4*)g_xpl)[base] = lv;
    float4* lxd = (float4*)(g_lxp + base * 8);
    lxd[0] = make_float4(lx[0], lx[1], lx[2], lx[3]);
    lxd[1] = make_float4(lx[4], lx[5], lx[6], lx[7]);
}

// ---------------- final combine + 1x1 conv ----------------
__global__ __launch_bounds__(256) void k_comfinal(float* __restrict__ out) {
    constexpr int H = 128, OH = 256;
    constexpr int stage = 3;
    int b = blockIdx.y;
    int p = blockIdx.x * 256 + threadIdx.x;
    int lane = threadIdx.x & 31;
    int Y = p >> 8, X = p & 255;
    int pp = (Y >> 1) * H + (X >> 1);
    __shared__ float sMn[3 * CH];
    __shared__ float sWo[3 * CH];
    __shared__ float sBo[3];
    if (threadIdx.x < 3 * CH) {
        int c = threadIdx.x & 7, which = threadIdx.x >> 3;
        const unsigned* src = which == 0 ? g_minpos : (which == 1 ? g_minneg : g_minmul);
        sMn[threadIdx.x] = __uint_as_float(src[stage * BATCH * CH + b * CH + c]);
        sWo[threadIdx.x] = g_wo[b * 24 + threadIdx.x];
    }
    if (threadIdx.x >= 32 && threadIdx.x < 35) sBo[threadIdx.x - 32] = g_bo[b * 3 + threadIdx.x - 32];
    __syncthreads();

    float dpv[CH];
    {
        float mydp[CH];
        if ((lane & 1) == 0) {
            const float4* p4 = (const float4*)(g_pos + ((size_t)b * H * H + pp) * 8);
            float4 a0 = p4[0], a1 = p4[1];
            float pv[8] = {a0.x, a0.y, a0.z, a0.w, a1.x, a1.y, a1.z, a1.w};
            #pragma unroll
            for (int c = 0; c < CH; c++) mydp[c] = dln_f(pv[c], sMn[c]);
        } else {
            #pragma unroll
            for (int c = 0; c < CH; c++) mydp[c] = 0.f;
        }
        #pragma unroll
        for (int c = 0; c < CH; c++)
            dpv[c] = __shfl_sync(0xFFFFFFFFu, mydp[c], lane & ~1);
    }

    const float4* n4 = (const float4*)(g_neg + ((size_t)b * OH * OH + p) * 8);
    const float4* m4 = (const float4*)(g_mul + ((size_t)b * OH * OH + p) * 8);
    float ng[8], ml[8];
    float4 a0 = n4[0], a1 = n4[1];
    ng[0]=a0.x; ng[1]=a0.y; ng[2]=a0.z; ng[3]=a0.w; ng[4]=a1.x; ng[5]=a1.y; ng[6]=a1.z; ng[7]=a1.w;
    a0 = m4[0]; a1 = m4[1];
    ml[0]=a0.x; ml[1]=a0.y; ml[2]=a0.z; ml[3]=a0.w; ml[4]=a1.x; ml[5]=a1.y; ml[6]=a1.z; ml[7]=a1.w;

    float acc[3] = {sBo[0], sBo[1], sBo[2]};
    #pragma unroll
    for (int c = 0; c < CH; c++) {
        float xv = (dpv[c] + dln_f(ng[c], sMn[8 + c])) * dln_f(ml[c], sMn[16 + c]);
        #pragma unroll
        for (int o = 0; o < 3; o++) acc[o] += sWo[o * CH + c] * xv;
    }
    #pragma unroll
    for (int o = 0; o < 3; o++)
        out[((size_t)b * 3 + o) * OH * OH + p] = acc[o];
}

// ---------------- launcher ----------------
extern "C" void kernel_launch(void* const* d_in, const int* in_sizes, int n_in,
                              void* d_out, int out_size) {
    const int*   ids = (const int*)  d_in[0];
    const float* cc  = (const float*)d_in[1];
    const float* lat = (const float*)d_in[2];
    const float* Wr = (const float*)d_in[3];
    const float* Ur = (const float*)d_in[4];
    const float* Vr = (const float*)d_in[5];
    const float* Br = (const float*)d_in[6];
    const float* Wt = (const float*)d_in[7];
    const float* Ut = (const float*)d_in[8];
    const float* Vt = (const float*)d_in[9];
    const float* Bt = (const float*)d_in[10];
    const float* Wm = (const float*)d_in[11];
    const float* Um = (const float*)d_in[12];
    const float* Vm = (const float*)d_in[13];
    const float* Bm = (const float*)d_in[14];
    const float* Wo = (const float*)d_in[15];
    const float* Uo = (const float*)d_in[16];
    const float* Vo = (const float*)d_in[17];
    const float* Bo = (const float*)d_in[18];

    k_gather<<<64, 256>>>(ids, cc, lat);
    k_weights<<<dim3(13, 64), 128>>>(Wr, Ur, Vr, Br, Wt, Ut, Vt, Bt,
                                     Wm, Um, Vm, Bm, Wo, Uo, Vo, Bo);

    // stage 0: H=16 (TH=8)
    k_mma<16><<<dim3(1, 4, 192), 256>>>(0);
    k_combineP<16><<<dim3(4, 64), 256>>>(0);
    // stage 1: H=32 (TH=8)
    k_mma<32><<<dim3(2, 8, 192), 256>>>(1);
    k_combineP<32><<<dim3(16, 64), 256>>>(1);
    // stage 2: H=64 (TH=16)
    k_mma<64><<<dim3(4, 8, 192), 256>>>(2);
    k_combineP<64><<<dim3(64, 64), 256>>>(2);
    // stage 3: H=128 (TH=16)
    k_mma<128><<<dim3(8, 16, 192), 256>>>(3);
    k_comfinal<<<dim3(256, 64), 256>>>((float*)d_out);
}